// round 16
// baseline (speedup 1.0000x reference)
#include <cuda_runtime.h>
#include <cuda_bf16.h>
#include <cstdint>

#define NUM_GRAPHS 512
#define C 128
#define CG (C / 4)           // 32 channel-groups of float4
#define THREADS 512
#define RPI (THREADS / CG)   // 16 rows per iteration
#define EPS 1e-5f
#define GRID 256
#define NPAIRS (GRID / 2)    // 128 clusters of 2
#define NSEG 4               // contiguous segments per pair
#define NH (2 * NSEG)        // 8 half-segments
#define W 2                  // producer lead allowance (halves)
#define NCRED (NH - W)       // 6 one-shot credit barriers

__device__ __forceinline__ uint32_t smem_u32(const void* p) {
    uint32_t a;
    asm("{ .reg .u64 t; cvta.to.shared.u64 t, %1; cvt.u32.u64 %0, t; }"
        : "=r"(a) : "l"(p));
    return a;
}
__device__ __forceinline__ uint32_t mapa_rank(uint32_t addr, uint32_t rank) {
    uint32_t r;
    asm("mapa.shared::cluster.u32 %0, %1, %2;" : "=r"(r) : "r"(addr), "r"(rank));
    return r;
}
__device__ __forceinline__ void st_dsmem_f32(uint32_t addr, float v) {
    asm volatile("st.shared::cluster.f32 [%0], %1;" :: "r"(addr), "f"(v) : "memory");
}
__device__ __forceinline__ void mbar_arrive_release_cluster(uint32_t addr) {
    asm volatile("mbarrier.arrive.release.cluster.shared::cluster.b64 _, [%0];"
                 :: "r"(addr) : "memory");
}
__device__ __forceinline__ void mbar_wait_parity(uint32_t addr, uint32_t par) {
    uint32_t done;
    do {
        asm volatile(
            "{\n\t.reg .pred p;\n\t"
            "mbarrier.try_wait.parity.acquire.cluster.shared::cta.b64 p, [%1], %2;\n\t"
            "selp.b32 %0, 1, 0, p;\n\t}"
            : "=r"(done) : "r"(addr), "r"(par) : "memory");
    } while (!done);
}
#define CLUSTER_SYNC() do { \
    asm volatile("barrier.cluster.arrive.aligned;" ::: "memory"); \
    asm volatile("barrier.cluster.wait.aligned;"   ::: "memory"); } while (0)

// Interpolation-guess + gallop: first idx with batch[idx] >= g.
__device__ __forceinline__ int find_bound(const int* __restrict__ batch, int n, int g) {
    if (g <= 0) return 0;
    int p = (int)(((long long)g * (long long)n) >> 9);
    if (p > n) p = n;
    int wlo = p, s = 512;
    while (wlo > 0 && batch[wlo - 1] >= g) { wlo -= s; if (wlo < 0) wlo = 0; s <<= 1; }
    int whi = p; s = 512;
    while (whi < n && batch[whi] < g)      { whi += s; if (whi > n) whi = n; s <<= 1; }
    while (wlo < whi) {
        int mid = (wlo + whi) >> 1;
        if (batch[mid] < g) wlo = mid + 1; else whi = mid;
    }
    return wlo;
}

#define ACC(v) do { \
    s0 += (v).x; s1 += (v).y; s2 += (v).z; s3 += (v).w; \
    q0 += (v).x * (v).x; q1 += (v).y * (v).y; \
    q2 += (v).z * (v).z; q3 += (v).w * (v).w; } while (0)

#define NORM_ST(v, idx) do { \
    (v).x = ((v).x - m.x) * iv.x * wv.x + bv.x; \
    (v).y = ((v).y - m.y) * iv.y * wv.y + bv.y; \
    (v).z = ((v).z - m.z) * iv.z * wv.z + bv.z; \
    (v).w = ((v).w - m.w) * iv.w * wv.w + bv.w; \
    __stcs(&op[(size_t)(idx) * CG + cg], (v)); } while (0)

__global__ __launch_bounds__(THREADS, 2) __cluster_dims__(2, 1, 1)
void graphnorm_kernel(const float* __restrict__ x,
                      const int*   __restrict__ batch,
                      const float* __restrict__ weight,
                      const float* __restrict__ bias,
                      float* __restrict__ out,
                      int n) {
    const int t    = threadIdx.x;
    const int cg   = t & (CG - 1);
    const int rw   = t >> 5;
    const int rank = blockIdx.x & 1;   // 0 = stats producer, 1 = normalizer
    const int pair = blockIdx.x >> 1;

    __shared__ int   s_bound[NSEG + 1];                    // contiguous segs 4p..4p+3
    __shared__ alignas(16) float s_sum[RPI][C];            // producer reduce scratch
    __shared__ alignas(16) float s_sq [RPI][C];
    __shared__ alignas(16) float s_stats[2][2][C];         // rx: [slot][mean|inv][C]
    __shared__ alignas(8) unsigned long long s_stat_mbar[2];
    __shared__ alignas(8) unsigned long long s_cred_mbar[NCRED];

    if (t <= NSEG)
        s_bound[t] = find_bound(batch, n, 4 * pair + t);

    const uint32_t statm_l = smem_u32(s_stat_mbar);
    const uint32_t credm_l = smem_u32(s_cred_mbar);
    if (t == 0) {
        #pragma unroll
        for (int s = 0; s < 2; s++)
            asm volatile("mbarrier.init.shared.b64 [%0], %1;"
                         :: "r"(statm_l + s * 8), "r"(32u) : "memory");
        #pragma unroll
        for (int k = 0; k < NCRED; k++)
            asm volatile("mbarrier.init.shared.b64 [%0], %1;"
                         :: "r"(credm_l + k * 8), "r"(32u) : "memory");
    }

    const float4 wv = ((const float4*)weight)[cg];
    const float4 bv = ((const float4*)bias)[cg];
    const float4* __restrict__ xp = (const float4*)x;
    float4* __restrict__       op = (float4*)out;

    const uint32_t stats_peer = mapa_rank(smem_u32(&s_stats[0][0][0]), rank ^ 1);
    const uint32_t statm_peer = mapa_rank(statm_l, rank ^ 1);
    const uint32_t credm_peer = mapa_rank(credm_l, rank ^ 1);

    __syncthreads();
    CLUSTER_SYNC();   // peer mbarrier init visible before any cross-CTA op

    if (rank == 0) {
        // ================= PRODUCER: pure read stream + stats =================
        float s0 = 0.f, s1 = 0.f, s2 = 0.f, s3 = 0.f;
        float q0 = 0.f, q1 = 0.f, q2 = 0.f, q3 = 0.f;
        for (int j = 0; j < NH; j++) {
            if (j >= W)   // backpressure: lead consumer by at most W halves
                mbar_wait_parity(credm_l + (uint32_t)(j - W) * 8, 0u);

            const int seg = j >> 1, hf = j & 1;
            const int st  = s_bound[seg], en = s_bound[seg + 1];
            const int mid = st + ((en - st) >> 1);
            const int lo  = hf ? mid : st;
            const int hi  = hf ? en  : mid;

            int r = lo + rw;
            for (; r + 3 * RPI < hi; r += 4 * RPI) {
                float4 a = __ldcg(&xp[(size_t)r * CG + cg]);
                float4 b = __ldcg(&xp[(size_t)(r + 1 * RPI) * CG + cg]);
                float4 c = __ldcg(&xp[(size_t)(r + 2 * RPI) * CG + cg]);
                float4 d = __ldcg(&xp[(size_t)(r + 3 * RPI) * CG + cg]);
                ACC(a); ACC(b); ACC(c); ACC(d);
            }
            for (; r < hi; r += RPI) {
                float4 v = __ldcg(&xp[(size_t)r * CG + cg]);
                ACC(v);
            }

            if (hf) {   // segment complete: reduce + push stats to consumer
                s_sum[rw][cg * 4 + 0] = s0; s_sum[rw][cg * 4 + 1] = s1;
                s_sum[rw][cg * 4 + 2] = s2; s_sum[rw][cg * 4 + 3] = s3;
                s_sq [rw][cg * 4 + 0] = q0; s_sq [rw][cg * 4 + 1] = q1;
                s_sq [rw][cg * 4 + 2] = q2; s_sq [rw][cg * 4 + 3] = q3;
                __syncthreads();
                if (rw == 0) {
                    float S0 = 0.f, S1 = 0.f, S2 = 0.f, S3 = 0.f;
                    float Q0 = 0.f, Q1 = 0.f, Q2 = 0.f, Q3 = 0.f;
                    #pragma unroll
                    for (int k = 0; k < RPI; k++) {
                        S0 += s_sum[k][cg * 4 + 0]; S1 += s_sum[k][cg * 4 + 1];
                        S2 += s_sum[k][cg * 4 + 2]; S3 += s_sum[k][cg * 4 + 3];
                        Q0 += s_sq [k][cg * 4 + 0]; Q1 += s_sq [k][cg * 4 + 1];
                        Q2 += s_sq [k][cg * 4 + 2]; Q3 += s_sq [k][cg * 4 + 3];
                    }
                    const float invc = 1.0f / (float)max(en - st, 1);
                    float m0 = S0 * invc, m1 = S1 * invc;
                    float m2 = S2 * invc, m3 = S3 * invc;
                    float i0 = rsqrtf(Q0 * invc - m0 * m0 + EPS);
                    float i1 = rsqrtf(Q1 * invc - m1 * m1 + EPS);
                    float i2 = rsqrtf(Q2 * invc - m2 * m2 + EPS);
                    float i3 = rsqrtf(Q3 * invc - m3 * m3 + EPS);
                    const int slot = seg & 1;
                    const uint32_t dst = stats_peer + (uint32_t)slot * (2 * C * 4)
                                                    + (uint32_t)cg * 16u;
                    st_dsmem_f32(dst +  0, m0); st_dsmem_f32(dst +  4, m1);
                    st_dsmem_f32(dst +  8, m2); st_dsmem_f32(dst + 12, m3);
                    st_dsmem_f32(dst + C * 4 +  0, i0);
                    st_dsmem_f32(dst + C * 4 +  4, i1);
                    st_dsmem_f32(dst + C * 4 +  8, i2);
                    st_dsmem_f32(dst + C * 4 + 12, i3);
                    mbar_arrive_release_cluster(statm_peer + (uint32_t)slot * 8);
                }
                __syncthreads();   // s_sum reuse guard
                s0 = s1 = s2 = s3 = q0 = q1 = q2 = q3 = 0.f;
            }
        }
    } else {
        // ================= CONSUMER: pure normalize/write stream =================
        for (int i = 0; i < NSEG; i++) {
            const int slot = i & 1;
            const uint32_t ph = (uint32_t)((i >> 1) & 1);
            mbar_wait_parity(statm_l + (uint32_t)slot * 8, ph);

            const float4 m  = ((const float4*)s_stats[slot][0])[cg];
            const float4 iv = ((const float4*)s_stats[slot][1])[cg];
            const int st  = s_bound[i], en = s_bound[i + 1];
            const int mid = st + ((en - st) >> 1);

            #pragma unroll
            for (int hf = 0; hf < 2; hf++) {
                const int lo = hf ? mid : st;
                const int hi = hf ? en  : mid;
                int r = lo + rw;
                for (; r + 3 * RPI < hi; r += 4 * RPI) {
                    float4 a = __ldcs(&xp[(size_t)r * CG + cg]);
                    float4 b = __ldcs(&xp[(size_t)(r + 1 * RPI) * CG + cg]);
                    float4 c = __ldcs(&xp[(size_t)(r + 2 * RPI) * CG + cg]);
                    float4 d = __ldcs(&xp[(size_t)(r + 3 * RPI) * CG + cg]);
                    NORM_ST(a, r);
                    NORM_ST(b, r + 1 * RPI);
                    NORM_ST(c, r + 2 * RPI);
                    NORM_ST(d, r + 3 * RPI);
                }
                for (; r < hi; r += RPI) {
                    float4 v = __ldcs(&xp[(size_t)r * CG + cg]);
                    NORM_ST(v, r);
                }
                const int k = 2 * i + hf;
                if (k < NCRED) {   // release one credit to producer
                    __syncthreads();
                    if (rw == 0)
                        mbar_arrive_release_cluster(credm_peer + (uint32_t)k * 8);
                }
            }
        }
    }

    CLUSTER_SYNC();   // neither CTA exits while peer may target its smem
}

extern "C" void kernel_launch(void* const* d_in, const int* in_sizes, int n_in,
                              void* d_out, int out_size) {
    const float* x      = (const float*)d_in[0];
    const int*   batch  = (const int*)d_in[1];
    const float* weight = (const float*)d_in[2];
    const float* bias   = (const float*)d_in[3];
    float*       out    = (float*)d_out;
    const int n = in_sizes[1];

    graphnorm_kernel<<<GRID, THREADS>>>(x, batch, weight, bias, out, n);
}